// round 2
// baseline (speedup 1.0000x reference)
#include <cuda_runtime.h>
#include <math.h>

// Problem constants
namespace {
constexpr int B_   = 16384;   // batch
constexpr int SD   = 128;     // state dim
constexpr int EK   = 10;      // encoder K
constexpr int K1   = SD * EK; // 1280
constexpr int H    = 2048;    // hidden (H0 == H1)
constexpr int N3   = 320;     // ACT_DIM * DEC_K
constexpr int AD   = 32;      // action dim
constexpr int DK   = 10;      // decoder K

// Tiling
constexpr int BM = 64, BN = 64, BK = 16;  // block tile
// 256 threads, each computes 4x4
}

// Scratch (no cudaMalloc allowed)
__device__ float g_h1[B_ * H];
__device__ float g_h2[B_ * H];
__device__ float g_a3[B_ * N3];

// ---------------------------------------------------------------------------
// GEMM1 with fused population-coding encoder for the A operand.
// out[b, n] = relu( sum_k sigmoid((state[b,d]-mean[d,kk])/std[d,kk]) * W[n,k] + bias[n] )
// where k = d*EK + kk. W is [H, K1] row-major (K contiguous) => C = A @ W^T.
// ---------------------------------------------------------------------------
__global__ __launch_bounds__(256) void gemm1_enc_kernel(
    const float* __restrict__ state, const float* __restrict__ mean,
    const float* __restrict__ stdv,  const float* __restrict__ W,
    const float* __restrict__ bias,  float* __restrict__ out)
{
    __shared__ float As[BK][BM];
    __shared__ float Bs[BK][BN];

    const int bm  = blockIdx.y * BM;
    const int bn  = blockIdx.x * BN;
    const int tid = threadIdx.x;
    const int tx  = tid & 15;      // 0..15 -> N
    const int ty  = tid >> 4;      // 0..15 -> M
    const int lr  = tid >> 2;      // load row 0..63
    const int lc  = (tid & 3) * 4; // load col base 0,4,8,12

    float acc[4][4] = {};

    for (int k0 = 0; k0 < K1; k0 += BK) {
        // --- A tile: compute encoder on the fly (row = batch, col = k) ---
        #pragma unroll
        for (int i = 0; i < 4; i++) {
            const int kidx = k0 + lc + i;
            const int d    = kidx / EK;
            const int kk   = kidx - d * EK;
            const float x  = (state[(bm + lr) * SD + d] - mean[d * EK + kk])
                             / stdv[d * EK + kk];
            As[lc + i][lr] = 1.0f / (1.0f + expf(-x));
        }
        // --- B tile: weights, vectorized ---
        const float4 w4 = *reinterpret_cast<const float4*>(
            &W[(bn + lr) * K1 + k0 + lc]);
        Bs[lc + 0][lr] = w4.x;
        Bs[lc + 1][lr] = w4.y;
        Bs[lc + 2][lr] = w4.z;
        Bs[lc + 3][lr] = w4.w;
        __syncthreads();

        #pragma unroll
        for (int kk = 0; kk < BK; kk++) {
            float a[4], b[4];
            #pragma unroll
            for (int i = 0; i < 4; i++) a[i] = As[kk][ty * 4 + i];
            #pragma unroll
            for (int j = 0; j < 4; j++) b[j] = Bs[kk][tx * 4 + j];
            #pragma unroll
            for (int i = 0; i < 4; i++)
                #pragma unroll
                for (int j = 0; j < 4; j++)
                    acc[i][j] = fmaf(a[i], b[j], acc[i][j]);
        }
        __syncthreads();
    }

    #pragma unroll
    for (int i = 0; i < 4; i++) {
        const int row = bm + ty * 4 + i;
        float4 v;
        float* vp = reinterpret_cast<float*>(&v);
        #pragma unroll
        for (int j = 0; j < 4; j++) {
            const int col = bn + tx * 4 + j;
            float t = acc[i][j] + bias[col];
            vp[j] = t > 0.0f ? t : 0.0f;
        }
        *reinterpret_cast<float4*>(&out[row * H + bn + tx * 4]) = v;
    }
}

// ---------------------------------------------------------------------------
// Generic C = A @ W^T + bias (optional ReLU). A: [B_, KDIM], W: [NDIM, KDIM].
// ---------------------------------------------------------------------------
template <int KDIM, int NDIM, bool RELU>
__global__ __launch_bounds__(256) void gemm_kernel(
    const float* __restrict__ A, const float* __restrict__ W,
    const float* __restrict__ bias, float* __restrict__ out)
{
    __shared__ float As[BK][BM];
    __shared__ float Bs[BK][BN];

    const int bm  = blockIdx.y * BM;
    const int bn  = blockIdx.x * BN;
    const int tid = threadIdx.x;
    const int tx  = tid & 15;
    const int ty  = tid >> 4;
    const int lr  = tid >> 2;
    const int lc  = (tid & 3) * 4;

    float acc[4][4] = {};

    for (int k0 = 0; k0 < KDIM; k0 += BK) {
        const float4 a4 = *reinterpret_cast<const float4*>(
            &A[(bm + lr) * KDIM + k0 + lc]);
        As[lc + 0][lr] = a4.x;
        As[lc + 1][lr] = a4.y;
        As[lc + 2][lr] = a4.z;
        As[lc + 3][lr] = a4.w;

        const float4 w4 = *reinterpret_cast<const float4*>(
            &W[(bn + lr) * KDIM + k0 + lc]);
        Bs[lc + 0][lr] = w4.x;
        Bs[lc + 1][lr] = w4.y;
        Bs[lc + 2][lr] = w4.z;
        Bs[lc + 3][lr] = w4.w;
        __syncthreads();

        #pragma unroll
        for (int kk = 0; kk < BK; kk++) {
            float a[4], b[4];
            #pragma unroll
            for (int i = 0; i < 4; i++) a[i] = As[kk][ty * 4 + i];
            #pragma unroll
            for (int j = 0; j < 4; j++) b[j] = Bs[kk][tx * 4 + j];
            #pragma unroll
            for (int i = 0; i < 4; i++)
                #pragma unroll
                for (int j = 0; j < 4; j++)
                    acc[i][j] = fmaf(a[i], b[j], acc[i][j]);
        }
        __syncthreads();
    }

    #pragma unroll
    for (int i = 0; i < 4; i++) {
        const int row = bm + ty * 4 + i;
        float4 v;
        float* vp = reinterpret_cast<float*>(&v);
        #pragma unroll
        for (int j = 0; j < 4; j++) {
            const int col = bn + tx * 4 + j;
            float t = acc[i][j] + bias[col];
            vp[j] = RELU ? (t > 0.0f ? t : 0.0f) : t;
        }
        *reinterpret_cast<float4*>(&out[row * NDIM + bn + tx * 4]) = v;
    }
}

// ---------------------------------------------------------------------------
// Decoder: out[b,a] = tanh( sum_j a3[b, a*DK+j] * Wd[a*DK+j] + bd[a] )
// (MAX_ACTION = 1.0)
// ---------------------------------------------------------------------------
__global__ __launch_bounds__(256) void decode_kernel(
    const float* __restrict__ a3, const float* __restrict__ Wd,
    const float* __restrict__ bd, float* __restrict__ out)
{
    const int idx = blockIdx.x * blockDim.x + threadIdx.x; // b*AD + a
    if (idx >= B_ * AD) return;
    const int b = idx >> 5;
    const int a = idx & 31;
    float s = bd[a];
    #pragma unroll
    for (int j = 0; j < DK; j++)
        s = fmaf(a3[b * N3 + a * DK + j], Wd[a * DK + j], s);
    out[idx] = tanhf(s);
}

extern "C" void kernel_launch(void* const* d_in, const int* in_sizes, int n_in,
                              void* d_out, int out_size)
{
    const float* state = (const float*)d_in[0];
    const float* mean  = (const float*)d_in[1];
    const float* stdv  = (const float*)d_in[2];
    const float* W1    = (const float*)d_in[3];
    const float* b1    = (const float*)d_in[4];
    const float* W2    = (const float*)d_in[5];
    const float* b2    = (const float*)d_in[6];
    const float* W3    = (const float*)d_in[7];
    const float* b3    = (const float*)d_in[8];
    const float* Wd    = (const float*)d_in[9];
    const float* bd    = (const float*)d_in[10];
    float* out = (float*)d_out;

    float *h1, *h2, *a3;
    cudaGetSymbolAddress((void**)&h1, g_h1);
    cudaGetSymbolAddress((void**)&h2, g_h2);
    cudaGetSymbolAddress((void**)&a3, g_a3);

    dim3 block(256);
    dim3 grid1(H / BN, B_ / BM);     // 32 x 256
    gemm1_enc_kernel<<<grid1, block>>>(state, mean, stdv, W1, b1, h1);

    dim3 grid2(H / BN, B_ / BM);     // 32 x 256
    gemm_kernel<H, H, true><<<grid2, block>>>(h1, W2, b2, h2);

    dim3 grid3(N3 / BN, B_ / BM);    // 5 x 256
    gemm_kernel<H, N3, false><<<grid3, block>>>(h2, W3, b3, a3);

    decode_kernel<<<(B_ * AD + 255) / 256, 256>>>(a3, Wd, bd, out);
}

// round 3
// speedup vs baseline: 1.0008x; 1.0008x over previous
#include <cuda_runtime.h>
#include <math.h>

// Problem constants
namespace {
constexpr int B_   = 16384;   // batch
constexpr int SD   = 128;     // state dim
constexpr int EK   = 10;      // encoder K
constexpr int K1   = SD * EK; // 1280
constexpr int H    = 2048;    // hidden (H0 == H1)
constexpr int N3   = 320;     // ACT_DIM * DEC_K
constexpr int AD   = 32;      // action dim
constexpr int DK   = 10;      // decoder K

// Tiling
constexpr int BM = 64, BN = 64, BK = 16;  // block tile
// 256 threads, each computes 4x4
}

// Scratch (no cudaMalloc allowed)
__device__ float g_h1[B_ * H];
__device__ float g_h2[B_ * H];
__device__ float g_a3[B_ * N3];

// ---------------------------------------------------------------------------
// GEMM1 with fused population-coding encoder for the A operand.
// out[b, n] = relu( sum_k sigmoid((state[b,d]-mean[d,kk])/std[d,kk]) * W[n,k] + bias[n] )
// where k = d*EK + kk. W is [H, K1] row-major (K contiguous) => C = A @ W^T.
// ---------------------------------------------------------------------------
__global__ __launch_bounds__(256) void gemm1_enc_kernel(
    const float* __restrict__ state, const float* __restrict__ mean,
    const float* __restrict__ stdv,  const float* __restrict__ W,
    const float* __restrict__ bias,  float* __restrict__ out)
{
    __shared__ float As[BK][BM];
    __shared__ float Bs[BK][BN];

    const int bm  = blockIdx.y * BM;
    const int bn  = blockIdx.x * BN;
    const int tid = threadIdx.x;
    const int tx  = tid & 15;      // 0..15 -> N
    const int ty  = tid >> 4;      // 0..15 -> M
    const int lr  = tid >> 2;      // load row 0..63
    const int lc  = (tid & 3) * 4; // load col base 0,4,8,12

    float acc[4][4] = {};

    for (int k0 = 0; k0 < K1; k0 += BK) {
        // --- A tile: compute encoder on the fly (row = batch, col = k) ---
        #pragma unroll
        for (int i = 0; i < 4; i++) {
            const int kidx = k0 + lc + i;
            const int d    = kidx / EK;
            const int kk   = kidx - d * EK;
            const float x  = (state[(bm + lr) * SD + d] - mean[d * EK + kk])
                             / stdv[d * EK + kk];
            As[lc + i][lr] = 1.0f / (1.0f + expf(-x));
        }
        // --- B tile: weights, vectorized ---
        const float4 w4 = *reinterpret_cast<const float4*>(
            &W[(bn + lr) * K1 + k0 + lc]);
        Bs[lc + 0][lr] = w4.x;
        Bs[lc + 1][lr] = w4.y;
        Bs[lc + 2][lr] = w4.z;
        Bs[lc + 3][lr] = w4.w;
        __syncthreads();

        #pragma unroll
        for (int kk = 0; kk < BK; kk++) {
            float a[4], b[4];
            #pragma unroll
            for (int i = 0; i < 4; i++) a[i] = As[kk][ty * 4 + i];
            #pragma unroll
            for (int j = 0; j < 4; j++) b[j] = Bs[kk][tx * 4 + j];
            #pragma unroll
            for (int i = 0; i < 4; i++)
                #pragma unroll
                for (int j = 0; j < 4; j++)
                    acc[i][j] = fmaf(a[i], b[j], acc[i][j]);
        }
        __syncthreads();
    }

    #pragma unroll
    for (int i = 0; i < 4; i++) {
        const int row = bm + ty * 4 + i;
        float4 v;
        float* vp = reinterpret_cast<float*>(&v);
        #pragma unroll
        for (int j = 0; j < 4; j++) {
            const int col = bn + tx * 4 + j;
            float t = acc[i][j] + bias[col];
            vp[j] = t > 0.0f ? t : 0.0f;
        }
        *reinterpret_cast<float4*>(&out[row * H + bn + tx * 4]) = v;
    }
}

// ---------------------------------------------------------------------------
// Generic C = A @ W^T + bias (optional ReLU). A: [B_, KDIM], W: [NDIM, KDIM].
// ---------------------------------------------------------------------------
template <int KDIM, int NDIM, bool RELU>
__global__ __launch_bounds__(256) void gemm_kernel(
    const float* __restrict__ A, const float* __restrict__ W,
    const float* __restrict__ bias, float* __restrict__ out)
{
    __shared__ float As[BK][BM];
    __shared__ float Bs[BK][BN];

    const int bm  = blockIdx.y * BM;
    const int bn  = blockIdx.x * BN;
    const int tid = threadIdx.x;
    const int tx  = tid & 15;
    const int ty  = tid >> 4;
    const int lr  = tid >> 2;
    const int lc  = (tid & 3) * 4;

    float acc[4][4] = {};

    for (int k0 = 0; k0 < KDIM; k0 += BK) {
        const float4 a4 = *reinterpret_cast<const float4*>(
            &A[(bm + lr) * KDIM + k0 + lc]);
        As[lc + 0][lr] = a4.x;
        As[lc + 1][lr] = a4.y;
        As[lc + 2][lr] = a4.z;
        As[lc + 3][lr] = a4.w;

        const float4 w4 = *reinterpret_cast<const float4*>(
            &W[(bn + lr) * KDIM + k0 + lc]);
        Bs[lc + 0][lr] = w4.x;
        Bs[lc + 1][lr] = w4.y;
        Bs[lc + 2][lr] = w4.z;
        Bs[lc + 3][lr] = w4.w;
        __syncthreads();

        #pragma unroll
        for (int kk = 0; kk < BK; kk++) {
            float a[4], b[4];
            #pragma unroll
            for (int i = 0; i < 4; i++) a[i] = As[kk][ty * 4 + i];
            #pragma unroll
            for (int j = 0; j < 4; j++) b[j] = Bs[kk][tx * 4 + j];
            #pragma unroll
            for (int i = 0; i < 4; i++)
                #pragma unroll
                for (int j = 0; j < 4; j++)
                    acc[i][j] = fmaf(a[i], b[j], acc[i][j]);
        }
        __syncthreads();
    }

    #pragma unroll
    for (int i = 0; i < 4; i++) {
        const int row = bm + ty * 4 + i;
        float4 v;
        float* vp = reinterpret_cast<float*>(&v);
        #pragma unroll
        for (int j = 0; j < 4; j++) {
            const int col = bn + tx * 4 + j;
            float t = acc[i][j] + bias[col];
            vp[j] = RELU ? (t > 0.0f ? t : 0.0f) : t;
        }
        *reinterpret_cast<float4*>(&out[row * NDIM + bn + tx * 4]) = v;
    }
}

// ---------------------------------------------------------------------------
// Decoder: out[b,a] = tanh( sum_j a3[b, a*DK+j] * Wd[a*DK+j] + bd[a] )
// (MAX_ACTION = 1.0)
// ---------------------------------------------------------------------------
__global__ __launch_bounds__(256) void decode_kernel(
    const float* __restrict__ a3, const float* __restrict__ Wd,
    const float* __restrict__ bd, float* __restrict__ out)
{
    const int idx = blockIdx.x * blockDim.x + threadIdx.x; // b*AD + a
    if (idx >= B_ * AD) return;
    const int b = idx >> 5;
    const int a = idx & 31;
    float s = bd[a];
    #pragma unroll
    for (int j = 0; j < DK; j++)
        s = fmaf(a3[b * N3 + a * DK + j], Wd[a * DK + j], s);
    out[idx] = tanhf(s);
}

extern "C" void kernel_launch(void* const* d_in, const int* in_sizes, int n_in,
                              void* d_out, int out_size)
{
    const float* state = (const float*)d_in[0];
    const float* mean  = (const float*)d_in[1];
    const float* stdv  = (const float*)d_in[2];
    const float* W1    = (const float*)d_in[3];
    const float* b1    = (const float*)d_in[4];
    const float* W2    = (const float*)d_in[5];
    const float* b2    = (const float*)d_in[6];
    const float* W3    = (const float*)d_in[7];
    const float* b3    = (const float*)d_in[8];
    const float* Wd    = (const float*)d_in[9];
    const float* bd    = (const float*)d_in[10];
    float* out = (float*)d_out;

    float *h1, *h2, *a3;
    cudaGetSymbolAddress((void**)&h1, g_h1);
    cudaGetSymbolAddress((void**)&h2, g_h2);
    cudaGetSymbolAddress((void**)&a3, g_a3);

    dim3 block(256);
    dim3 grid1(H / BN, B_ / BM);     // 32 x 256
    gemm1_enc_kernel<<<grid1, block>>>(state, mean, stdv, W1, b1, h1);

    dim3 grid2(H / BN, B_ / BM);     // 32 x 256
    gemm_kernel<H, H, true><<<grid2, block>>>(h1, W2, b2, h2);

    dim3 grid3(N3 / BN, B_ / BM);    // 5 x 256
    gemm_kernel<H, N3, false><<<grid3, block>>>(h2, W3, b3, a3);

    decode_kernel<<<(B_ * AD + 255) / 256, 256>>>(a3, Wd, bd, out);
}

// round 5
// speedup vs baseline: 4.7770x; 4.7734x over previous
#include <cuda_runtime.h>
#include <math.h>
#include <stdint.h>

// ---------------------------------------------------------------------------
// Problem constants
// ---------------------------------------------------------------------------
namespace {
constexpr int B_  = 16384;
constexpr int SD  = 128;
constexpr int EK  = 10;
constexpr int K1  = SD * EK;   // 1280
constexpr int H   = 2048;
constexpr int N3  = 320;
constexpr int AD  = 32;
constexpr int DK  = 10;

constexpr int BM     = 128;
constexpr int BK     = 32;
constexpr int PAD    = 4;
constexpr int LDA    = BK + PAD;   // 36 floats row stride in smem
constexpr int STAGES = 3;

constexpr int TBL    = 4096;
constexpr float TRNG = 14.0f;
}

// Scratch (no cudaMalloc allowed)
__device__ float g_spine[B_ * K1];
__device__ float g_h1[B_ * H];
__device__ float g_h2[B_ * H];
__device__ float g_a3[B_ * N3];
__device__ float g_table[TBL + 1];
__device__ float g_rstd[K1];

// ---------------------------------------------------------------------------
// PTX helpers (sm_80+ only — NO tcgen05; harness targets compute_100)
// ---------------------------------------------------------------------------
__device__ __forceinline__ uint32_t smem_u32(const void* p) {
    uint32_t a;
    asm("{ .reg .u64 t; cvta.to.shared.u64 t, %1; cvt.u32.u64 %0, t; }"
        : "=r"(a) : "l"(p));
    return a;
}
__device__ __forceinline__ void cp_async16(uint32_t dst, const void* src) {
    asm volatile("cp.async.cg.shared.global [%0], [%1], 16;\n"
                 :: "r"(dst), "l"(src));
}
__device__ __forceinline__ void cp_commit() {
    asm volatile("cp.async.commit_group;\n" ::: "memory");
}
template <int N>
__device__ __forceinline__ void cp_wait_group() {
    asm volatile("cp.async.wait_group %0;\n" :: "n"(N) : "memory");
}
__device__ __forceinline__ uint32_t cvt_tf32(float x) {
    uint32_t r;
    asm("cvt.rna.tf32.f32 %0, %1;" : "=r"(r) : "f"(x));
    return r;
}
__device__ __forceinline__ void mma_tf32(float* c, const uint32_t* a,
                                         const uint32_t* b) {
    asm volatile(
        "mma.sync.aligned.m16n8k8.row.col.f32.tf32.tf32.f32 "
        "{%0,%1,%2,%3}, {%4,%5,%6,%7}, {%8,%9}, {%0,%1,%2,%3};"
        : "+f"(c[0]), "+f"(c[1]), "+f"(c[2]), "+f"(c[3])
        : "r"(a[0]), "r"(a[1]), "r"(a[2]), "r"(a[3]), "r"(b[0]), "r"(b[1]));
}

// ---------------------------------------------------------------------------
// Init: sigmoid table + reciprocal std
// ---------------------------------------------------------------------------
__global__ void init_tables_kernel(const float* __restrict__ stdv) {
    const int i = blockIdx.x * blockDim.x + threadIdx.x;
    if (i <= TBL) {
        const float x = -TRNG + (2.0f * TRNG) * (float)i / (float)TBL;
        g_table[i] = 1.0f / (1.0f + expf(-x));
    }
    if (i < K1) g_rstd[i] = 1.0f / stdv[i];
}

// ---------------------------------------------------------------------------
// Encoder: spine[b, d*EK+kk] = sigmoid((state[b,d]-mean[k]) * rstd[k])
// via SMEM linear-interp table (no MUFU on the hot path).
// ---------------------------------------------------------------------------
__global__ __launch_bounds__(256) void encode_kernel(
    const float* __restrict__ state, const float* __restrict__ mean,
    float* __restrict__ spine)
{
    __shared__ float tbl[TBL + 4];
    __shared__ float s_mean[K1];
    __shared__ float s_rstd[K1];
    for (int i = threadIdx.x; i <= TBL; i += 256) tbl[i] = g_table[i];
    for (int i = threadIdx.x; i < K1; i += 256) {
        s_mean[i] = mean[i];
        s_rstd[i] = g_rstd[i];
    }
    __syncthreads();

    constexpr float SCALE = (float)TBL / (2.0f * TRNG);
    const int total4 = B_ * K1 / 4;
    for (int idx4 = blockIdx.x * blockDim.x + threadIdx.x; idx4 < total4;
         idx4 += gridDim.x * blockDim.x) {
        const int base = idx4 * 4;
        const int b  = base / K1;
        const int k0 = base - b * K1;
        float4 o;
        float* op = reinterpret_cast<float*>(&o);
        #pragma unroll
        for (int j = 0; j < 4; j++) {
            const int k = k0 + j;
            const int d = k / EK;
            const float x = (state[b * SD + d] - s_mean[k]) * s_rstd[k];
            float t = (x + TRNG) * SCALE;
            t = fminf(fmaxf(t, 0.0f), (float)TBL - 0.0001f);
            const int i = (int)t;
            const float f = t - (float)i;
            op[j] = fmaf(f, tbl[i + 1] - tbl[i], tbl[i]);
        }
        *reinterpret_cast<float4*>(&spine[base]) = o;
    }
}

// ---------------------------------------------------------------------------
// tf32 mma.sync GEMM: out = act(A @ W^T + bias)
//   A [B_, KDIM] row-major, W [NDIM, KDIM] row-major.
//   Tile BM x BN x 32, 8 warps (2 M x 4 N), warp tile 64 x (BN/4).
//   3-stage cp.async pipeline. Smem tiles m-major [rows][BK+4] (conflict-free).
// ---------------------------------------------------------------------------
template <int BN, int NDIM, int KDIM, bool RELU>
__global__ __launch_bounds__(256, 2) void gemm_mma(
    const float* __restrict__ A, const float* __restrict__ W,
    const float* __restrict__ bias, float* __restrict__ out)
{
    constexpr int STRIDE = (BM + BN) * LDA;   // floats per stage
    constexpr int NT = BN / 32;               // n-tiles of 8 per warp (4 or 2)
    constexpr int nK = KDIM / BK;
    extern __shared__ float sm[];

    const int tid  = threadIdx.x;
    const int lane = tid & 31;
    const int wid  = tid >> 5;
    const int bm = blockIdx.y * BM;
    const int bn = blockIdx.x * BN;
    const int wm = (wid >> 2) * 64;           // warp M offset in tile
    const int wn = (wid & 3) * (BN / 4);      // warp N offset in tile
    const int ar = lane >> 2;                 // fragment row (0..7)
    const int ac = lane & 3;                  // fragment col (0..3)

    float acc[4][NT][4];
    #pragma unroll
    for (int i = 0; i < 4; i++)
        #pragma unroll
        for (int j = 0; j < NT; j++)
            #pragma unroll
            for (int m = 0; m < 4; m++) acc[i][j][m] = 0.0f;

    auto load_stage = [&](int s, int kc) {
        float* As = sm + s * STRIDE;
        float* Bs = As + BM * LDA;
        const int k0 = kc * BK;
        #pragma unroll 4
        for (int q = tid; q < BM * 8; q += 256) {
            const int r = q >> 3, c = q & 7;
            cp_async16(smem_u32(As + r * LDA + c * 4),
                       A + (size_t)(bm + r) * KDIM + k0 + c * 4);
        }
        #pragma unroll 4
        for (int q = tid; q < BN * 8; q += 256) {
            const int r = q >> 3, c = q & 7;
            cp_async16(smem_u32(Bs + r * LDA + c * 4),
                       W + (size_t)(bn + r) * KDIM + k0 + c * 4);
        }
    };

    #pragma unroll
    for (int s = 0; s < STAGES - 1; s++) { load_stage(s, s); cp_commit(); }

    for (int k = 0; k < nK; k++) {
        cp_wait_group<STAGES - 2>();
        __syncthreads();

        const float* As = sm + (k % STAGES) * STRIDE;
        const float* Bs = As + BM * LDA;
        #pragma unroll
        for (int kk = 0; kk < BK / 8; kk++) {
            uint32_t af[4][4], bf[NT][2];
            #pragma unroll
            for (int tm = 0; tm < 4; tm++) {
                const float* p = As + (wm + tm * 16 + ar) * LDA + kk * 8 + ac;
                af[tm][0] = cvt_tf32(p[0]);
                af[tm][1] = cvt_tf32(p[8 * LDA]);
                af[tm][2] = cvt_tf32(p[4]);
                af[tm][3] = cvt_tf32(p[8 * LDA + 4]);
            }
            #pragma unroll
            for (int tn = 0; tn < NT; tn++) {
                const float* p = Bs + (wn + tn * 8 + ar) * LDA + kk * 8 + ac;
                bf[tn][0] = cvt_tf32(p[0]);
                bf[tn][1] = cvt_tf32(p[4]);
            }
            #pragma unroll
            for (int tm = 0; tm < 4; tm++)
                #pragma unroll
                for (int tn = 0; tn < NT; tn++)
                    mma_tf32(acc[tm][tn], af[tm], bf[tn]);
        }

        const int kn = k + STAGES - 1;
        if (kn < nK) load_stage((kn) % STAGES, kn);
        cp_commit();
    }

    // Epilogue: bias + activation, float2 stores straight from registers.
    #pragma unroll
    for (int tm = 0; tm < 4; tm++) {
        const int row0 = bm + wm + tm * 16 + ar;
        #pragma unroll
        for (int tn = 0; tn < NT; tn++) {
            const int col = bn + wn + tn * 8 + ac * 2;
            const float bx = bias[col];
            const float by = bias[col + 1];
            float* c = acc[tm][tn];
            float2 v0, v1;
            v0.x = c[0] + bx; v0.y = c[1] + by;
            v1.x = c[2] + bx; v1.y = c[3] + by;
            if (RELU) {
                v0.x = v0.x > 0.0f ? v0.x : 0.0f;
                v0.y = v0.y > 0.0f ? v0.y : 0.0f;
                v1.x = v1.x > 0.0f ? v1.x : 0.0f;
                v1.y = v1.y > 0.0f ? v1.y : 0.0f;
            }
            *reinterpret_cast<float2*>(&out[(size_t)row0 * NDIM + col]) = v0;
            *reinterpret_cast<float2*>(&out[(size_t)(row0 + 8) * NDIM + col]) = v1;
        }
    }
}

// ---------------------------------------------------------------------------
// Decoder: out[b,a] = tanh(sum_j a3[b, a*DK+j] * Wd[a*DK+j] + bd[a])
// ---------------------------------------------------------------------------
__global__ __launch_bounds__(256) void decode_kernel(
    const float* __restrict__ a3, const float* __restrict__ Wd,
    const float* __restrict__ bd, float* __restrict__ out)
{
    const int idx = blockIdx.x * blockDim.x + threadIdx.x;
    if (idx >= B_ * AD) return;
    const int b = idx >> 5;
    const int a = idx & 31;
    float s = bd[a];
    #pragma unroll
    for (int j = 0; j < DK; j++)
        s = fmaf(a3[b * N3 + a * DK + j], Wd[a * DK + j], s);
    out[idx] = tanhf(s);
}

// ---------------------------------------------------------------------------
extern "C" void kernel_launch(void* const* d_in, const int* in_sizes, int n_in,
                              void* d_out, int out_size)
{
    const float* state = (const float*)d_in[0];
    const float* mean  = (const float*)d_in[1];
    const float* stdv  = (const float*)d_in[2];
    const float* W1    = (const float*)d_in[3];
    const float* b1    = (const float*)d_in[4];
    const float* W2    = (const float*)d_in[5];
    const float* b2    = (const float*)d_in[6];
    const float* W3    = (const float*)d_in[7];
    const float* b3    = (const float*)d_in[8];
    const float* Wd    = (const float*)d_in[9];
    const float* bd    = (const float*)d_in[10];
    float* out = (float*)d_out;

    float *spine, *h1, *h2, *a3;
    cudaGetSymbolAddress((void**)&spine, g_spine);
    cudaGetSymbolAddress((void**)&h1, g_h1);
    cudaGetSymbolAddress((void**)&h2, g_h2);
    cudaGetSymbolAddress((void**)&a3, g_a3);

    constexpr int SMEM_128 = STAGES * (BM + 128) * LDA * sizeof(float); // 110592
    constexpr int SMEM_64  = STAGES * (BM + 64)  * LDA * sizeof(float); //  82944
    static bool attr_done = false;
    if (!attr_done) {
        cudaFuncSetAttribute(gemm_mma<128, H, K1, true>,
                             cudaFuncAttributeMaxDynamicSharedMemorySize, SMEM_128);
        cudaFuncSetAttribute(gemm_mma<128, H, H, true>,
                             cudaFuncAttributeMaxDynamicSharedMemorySize, SMEM_128);
        cudaFuncSetAttribute(gemm_mma<64, N3, H, false>,
                             cudaFuncAttributeMaxDynamicSharedMemorySize, SMEM_64);
        attr_done = true;
    }

    init_tables_kernel<<<(TBL + 256) / 256, 256>>>(stdv);
    encode_kernel<<<2048, 256>>>(state, mean, spine);

    dim3 blk(256);
    gemm_mma<128, H, K1, true>
        <<<dim3(H / 128, B_ / BM), blk, SMEM_128>>>(spine, W1, b1, h1);
    gemm_mma<128, H, H, true>
        <<<dim3(H / 128, B_ / BM), blk, SMEM_128>>>(h1, W2, b2, h2);
    gemm_mma<64, N3, H, false>
        <<<dim3(N3 / 64, B_ / BM), blk, SMEM_64>>>(h2, W3, b3, a3);

    decode_kernel<<<(B_ * AD + 255) / 256, 256>>>(a3, Wd, bd, out);
}

// round 6
// speedup vs baseline: 4.8573x; 1.0168x over previous
#include <cuda_runtime.h>
#include <math.h>
#include <stdint.h>

// ---------------------------------------------------------------------------
// Problem constants
// ---------------------------------------------------------------------------
namespace {
constexpr int B_  = 16384;
constexpr int SD  = 128;
constexpr int EK  = 10;
constexpr int K1  = SD * EK;   // 1280
constexpr int H   = 2048;
constexpr int N3  = 320;
constexpr int AD  = 32;
constexpr int DK  = 10;

constexpr int BM     = 128;
constexpr int BK     = 32;
constexpr int PAD    = 4;
constexpr int LDA    = BK + PAD;   // 36-float smem row stride
constexpr int STAGES = 3;

constexpr int TBL    = 4096;
constexpr float TRNG = 14.0f;
}

// Scratch (no cudaMalloc allowed)
__device__ float g_spine[B_ * K1];
__device__ float g_h1[B_ * H];
__device__ float g_h2[B_ * H];
__device__ float g_a3[B_ * N3];
__device__ float g_w1[H * K1];
__device__ float g_w2[H * H];
__device__ float g_w3[N3 * H];
__device__ float g_table[TBL + 1];
__device__ float g_rstd[K1];

// ---------------------------------------------------------------------------
// PTX helpers (sm_80+ only — harness targets compute_100, no tcgen05)
// ---------------------------------------------------------------------------
__device__ __forceinline__ uint32_t smem_u32(const void* p) {
    uint32_t a;
    asm("{ .reg .u64 t; cvta.to.shared.u64 t, %1; cvt.u32.u64 %0, t; }"
        : "=r"(a) : "l"(p));
    return a;
}
__device__ __forceinline__ void cp_async16(uint32_t dst, const void* src) {
    asm volatile("cp.async.cg.shared.global [%0], [%1], 16;\n"
                 :: "r"(dst), "l"(src));
}
__device__ __forceinline__ void cp_commit() {
    asm volatile("cp.async.commit_group;\n" ::: "memory");
}
template <int N>
__device__ __forceinline__ void cp_wait_group() {
    asm volatile("cp.async.wait_group %0;\n" :: "n"(N) : "memory");
}
__device__ __forceinline__ float cvt_tf32_f(float x) {
    uint32_t r;
    asm("cvt.rna.tf32.f32 %0, %1;" : "=r"(r) : "f"(x));
    return __uint_as_float(r);
}
// Operands pre-rounded to tf32 (RNA) in memory -> feed raw bits, HW RZ is identity.
__device__ __forceinline__ void mma_tf32(float* c, const uint32_t* a,
                                         const uint32_t* b) {
    asm volatile(
        "mma.sync.aligned.m16n8k8.row.col.f32.tf32.tf32.f32 "
        "{%0,%1,%2,%3}, {%4,%5,%6,%7}, {%8,%9}, {%0,%1,%2,%3};"
        : "+f"(c[0]), "+f"(c[1]), "+f"(c[2]), "+f"(c[3])
        : "r"(a[0]), "r"(a[1]), "r"(a[2]), "r"(a[3]), "r"(b[0]), "r"(b[1]));
}

// ---------------------------------------------------------------------------
// Init: sigmoid table + reciprocal std
// ---------------------------------------------------------------------------
__global__ void init_tables_kernel(const float* __restrict__ stdv) {
    const int i = blockIdx.x * blockDim.x + threadIdx.x;
    if (i <= TBL) {
        const float x = -TRNG + (2.0f * TRNG) * (float)i / (float)TBL;
        g_table[i] = 1.0f / (1.0f + expf(-x));
    }
    if (i < K1) g_rstd[i] = 1.0f / stdv[i];
}

// ---------------------------------------------------------------------------
// RNA-round weights into scratch (once per launch; ~10us for 30MB)
// ---------------------------------------------------------------------------
__global__ __launch_bounds__(256) void round_weights_kernel(
    const float* __restrict__ w1, const float* __restrict__ w2,
    const float* __restrict__ w3)
{
    constexpr int N1 = H * K1, N2 = H * H, N3E = N3 * H;
    const int stride = gridDim.x * blockDim.x;
    for (int i = blockIdx.x * blockDim.x + threadIdx.x; i < N1 / 4; i += stride) {
        float4 v = reinterpret_cast<const float4*>(w1)[i];
        v.x = cvt_tf32_f(v.x); v.y = cvt_tf32_f(v.y);
        v.z = cvt_tf32_f(v.z); v.w = cvt_tf32_f(v.w);
        reinterpret_cast<float4*>(g_w1)[i] = v;
    }
    for (int i = blockIdx.x * blockDim.x + threadIdx.x; i < N2 / 4; i += stride) {
        float4 v = reinterpret_cast<const float4*>(w2)[i];
        v.x = cvt_tf32_f(v.x); v.y = cvt_tf32_f(v.y);
        v.z = cvt_tf32_f(v.z); v.w = cvt_tf32_f(v.w);
        reinterpret_cast<float4*>(g_w2)[i] = v;
    }
    for (int i = blockIdx.x * blockDim.x + threadIdx.x; i < N3E / 4; i += stride) {
        float4 v = reinterpret_cast<const float4*>(w3)[i];
        v.x = cvt_tf32_f(v.x); v.y = cvt_tf32_f(v.y);
        v.z = cvt_tf32_f(v.z); v.w = cvt_tf32_f(v.w);
        reinterpret_cast<float4*>(g_w3)[i] = v;
    }
}

// ---------------------------------------------------------------------------
// Encoder: spine = tf32_rna(sigmoid((state - mean) * rstd)) via interp table
// ---------------------------------------------------------------------------
__global__ __launch_bounds__(256) void encode_kernel(
    const float* __restrict__ state, const float* __restrict__ mean,
    float* __restrict__ spine)
{
    __shared__ float tbl[TBL + 4];
    __shared__ float s_mean[K1];
    __shared__ float s_rstd[K1];
    for (int i = threadIdx.x; i <= TBL; i += 256) tbl[i] = g_table[i];
    for (int i = threadIdx.x; i < K1; i += 256) {
        s_mean[i] = mean[i];
        s_rstd[i] = g_rstd[i];
    }
    __syncthreads();

    constexpr float SCALE = (float)TBL / (2.0f * TRNG);
    const int total4 = B_ * K1 / 4;
    for (int idx4 = blockIdx.x * blockDim.x + threadIdx.x; idx4 < total4;
         idx4 += gridDim.x * blockDim.x) {
        const int base = idx4 * 4;
        const int b  = base / K1;
        const int k0 = base - b * K1;
        float4 o;
        float* op = reinterpret_cast<float*>(&o);
        #pragma unroll
        for (int j = 0; j < 4; j++) {
            const int k = k0 + j;
            const int d = k / EK;
            const float x = (state[b * SD + d] - s_mean[k]) * s_rstd[k];
            float t = (x + TRNG) * SCALE;
            t = fminf(fmaxf(t, 0.0f), (float)TBL - 0.0001f);
            const int i = (int)t;
            const float f = t - (float)i;
            op[j] = cvt_tf32_f(fmaf(f, tbl[i + 1] - tbl[i], tbl[i]));
        }
        *reinterpret_cast<float4*>(&spine[base]) = o;
    }
}

// ---------------------------------------------------------------------------
// tf32 mma.sync GEMM: out = act(A @ W^T + bias)
//   Operands pre-rounded to tf32; inner loop has ZERO cvt instructions.
//   Tile BM x BN x 32, 8 warps (2 M x 4 N), 3-stage cp.async pipeline,
//   next-stage loads issued BEFORE compute for 2-iteration latency slack.
//   ROUND_OUT: RNA-round outputs (they feed the next tf32 GEMM).
// ---------------------------------------------------------------------------
template <int BN, int NDIM, int KDIM, bool RELU, bool ROUND_OUT>
__global__ __launch_bounds__(256, 2) void gemm_mma(
    const float* __restrict__ A, const float* __restrict__ W,
    const float* __restrict__ bias, float* __restrict__ out)
{
    constexpr int STRIDE = (BM + BN) * LDA;
    constexpr int NT = BN / 32;
    constexpr int nK = KDIM / BK;
    extern __shared__ float sm[];

    const int tid  = threadIdx.x;
    const int lane = tid & 31;
    const int wid  = tid >> 5;
    const int bm = blockIdx.y * BM;
    const int bn = blockIdx.x * BN;
    const int wm = (wid >> 2) * 64;
    const int wn = (wid & 3) * (BN / 4);
    const int ar = lane >> 2;
    const int ac = lane & 3;

    float acc[4][NT][4];
    #pragma unroll
    for (int i = 0; i < 4; i++)
        #pragma unroll
        for (int j = 0; j < NT; j++)
            #pragma unroll
            for (int m = 0; m < 4; m++) acc[i][j][m] = 0.0f;

    auto load_stage = [&](int s, int kc) {
        float* As = sm + s * STRIDE;
        float* Bs = As + BM * LDA;
        const int k0 = kc * BK;
        #pragma unroll 4
        for (int q = tid; q < BM * 8; q += 256) {
            const int r = q >> 3, c = q & 7;
            cp_async16(smem_u32(As + r * LDA + c * 4),
                       A + (size_t)(bm + r) * KDIM + k0 + c * 4);
        }
        #pragma unroll 4
        for (int q = tid; q < BN * 8; q += 256) {
            const int r = q >> 3, c = q & 7;
            cp_async16(smem_u32(Bs + r * LDA + c * 4),
                       W + (size_t)(bn + r) * KDIM + k0 + c * 4);
        }
    };

    #pragma unroll
    for (int s = 0; s < STAGES - 1; s++) { load_stage(s, s); cp_commit(); }

    for (int k = 0; k < nK; k++) {
        cp_wait_group<STAGES - 2>();
        __syncthreads();

        // Issue next-stage loads FIRST (overwrites the stage consumed at k-1,
        // safe after the barrier above), then compute the current stage.
        const int kn = k + STAGES - 1;
        if (kn < nK) load_stage(kn % STAGES, kn);
        cp_commit();

        const float* As = sm + (k % STAGES) * STRIDE;
        const float* Bs = As + BM * LDA;
        #pragma unroll
        for (int kk = 0; kk < BK / 8; kk++) {
            uint32_t af[4][4], bf[NT][2];
            #pragma unroll
            for (int tm = 0; tm < 4; tm++) {
                const uint32_t* p = reinterpret_cast<const uint32_t*>(
                    As + (wm + tm * 16 + ar) * LDA + kk * 8 + ac);
                af[tm][0] = p[0];
                af[tm][1] = p[8 * LDA];
                af[tm][2] = p[4];
                af[tm][3] = p[8 * LDA + 4];
            }
            #pragma unroll
            for (int tn = 0; tn < NT; tn++) {
                const uint32_t* p = reinterpret_cast<const uint32_t*>(
                    Bs + (wn + tn * 8 + ar) * LDA + kk * 8 + ac);
                bf[tn][0] = p[0];
                bf[tn][1] = p[4];
            }
            #pragma unroll
            for (int tm = 0; tm < 4; tm++)
                #pragma unroll
                for (int tn = 0; tn < NT; tn++)
                    mma_tf32(acc[tm][tn], af[tm], bf[tn]);
        }
    }

    // Epilogue: bias + activation (+ optional tf32 rounding), float2 stores.
    #pragma unroll
    for (int tm = 0; tm < 4; tm++) {
        const int row0 = bm + wm + tm * 16 + ar;
        #pragma unroll
        for (int tn = 0; tn < NT; tn++) {
            const int col = bn + wn + tn * 8 + ac * 2;
            const float bx = bias[col];
            const float by = bias[col + 1];
            float* c = acc[tm][tn];
            float2 v0, v1;
            v0.x = c[0] + bx; v0.y = c[1] + by;
            v1.x = c[2] + bx; v1.y = c[3] + by;
            if (RELU) {
                v0.x = v0.x > 0.0f ? v0.x : 0.0f;
                v0.y = v0.y > 0.0f ? v0.y : 0.0f;
                v1.x = v1.x > 0.0f ? v1.x : 0.0f;
                v1.y = v1.y > 0.0f ? v1.y : 0.0f;
            }
            if (ROUND_OUT) {
                v0.x = cvt_tf32_f(v0.x); v0.y = cvt_tf32_f(v0.y);
                v1.x = cvt_tf32_f(v1.x); v1.y = cvt_tf32_f(v1.y);
            }
            *reinterpret_cast<float2*>(&out[(size_t)row0 * NDIM + col]) = v0;
            *reinterpret_cast<float2*>(&out[(size_t)(row0 + 8) * NDIM + col]) = v1;
        }
    }
}

// ---------------------------------------------------------------------------
// Decoder: out[b,a] = tanh(sum_j a3[b, a*DK+j] * Wd[a*DK+j] + bd[a])
// ---------------------------------------------------------------------------
__global__ __launch_bounds__(256) void decode_kernel(
    const float* __restrict__ a3, const float* __restrict__ Wd,
    const float* __restrict__ bd, float* __restrict__ out)
{
    const int idx = blockIdx.x * blockDim.x + threadIdx.x;
    if (idx >= B_ * AD) return;
    const int b = idx >> 5;
    const int a = idx & 31;
    float s = bd[a];
    #pragma unroll
    for (int j = 0; j < DK; j++)
        s = fmaf(a3[b * N3 + a * DK + j], Wd[a * DK + j], s);
    out[idx] = tanhf(s);
}

// ---------------------------------------------------------------------------
extern "C" void kernel_launch(void* const* d_in, const int* in_sizes, int n_in,
                              void* d_out, int out_size)
{
    const float* state = (const float*)d_in[0];
    const float* mean  = (const float*)d_in[1];
    const float* stdv  = (const float*)d_in[2];
    const float* W1    = (const float*)d_in[3];
    const float* b1    = (const float*)d_in[4];
    const float* W2    = (const float*)d_in[5];
    const float* b2    = (const float*)d_in[6];
    const float* W3    = (const float*)d_in[7];
    const float* b3    = (const float*)d_in[8];
    const float* Wd    = (const float*)d_in[9];
    const float* bd    = (const float*)d_in[10];
    float* out = (float*)d_out;

    float *spine, *h1, *h2, *a3, *w1r, *w2r, *w3r;
    cudaGetSymbolAddress((void**)&spine, g_spine);
    cudaGetSymbolAddress((void**)&h1, g_h1);
    cudaGetSymbolAddress((void**)&h2, g_h2);
    cudaGetSymbolAddress((void**)&a3, g_a3);
    cudaGetSymbolAddress((void**)&w1r, g_w1);
    cudaGetSymbolAddress((void**)&w2r, g_w2);
    cudaGetSymbolAddress((void**)&w3r, g_w3);

    constexpr int SMEM_128 = STAGES * (BM + 128) * LDA * sizeof(float); // 110592
    constexpr int SMEM_64  = STAGES * (BM + 64)  * LDA * sizeof(float); //  82944
    static bool attr_done = false;
    if (!attr_done) {
        cudaFuncSetAttribute(gemm_mma<128, H, K1, true, true>,
                             cudaFuncAttributeMaxDynamicSharedMemorySize, SMEM_128);
        cudaFuncSetAttribute(gemm_mma<128, H, H, true, true>,
                             cudaFuncAttributeMaxDynamicSharedMemorySize, SMEM_128);
        cudaFuncSetAttribute(gemm_mma<64, N3, H, false, false>,
                             cudaFuncAttributeMaxDynamicSharedMemorySize, SMEM_64);
        attr_done = true;
    }

    init_tables_kernel<<<(TBL + 256) / 256, 256>>>(stdv);
    round_weights_kernel<<<1024, 256>>>(W1, W2, W3);
    encode_kernel<<<2048, 256>>>(state, mean, spine);

    dim3 blk(256);
    gemm_mma<128, H, K1, true, true>
        <<<dim3(H / 128, B_ / BM), blk, SMEM_128>>>(spine, w1r, b1, h1);
    gemm_mma<128, H, H, true, true>
        <<<dim3(H / 128, B_ / BM), blk, SMEM_128>>>(h1, w2r, b2, h2);
    gemm_mma<64, N3, H, false, false>
        <<<dim3(N3 / 64, B_ / BM), blk, SMEM_64>>>(h2, w3r, b3, a3);

    decode_kernel<<<(B_ * AD + 255) / 256, 256>>>(a3, Wd, bd, out);
}

// round 7
// speedup vs baseline: 5.3636x; 1.1042x over previous
#include <cuda_runtime.h>
#include <math.h>
#include <stdint.h>

// ---------------------------------------------------------------------------
// Problem constants
// ---------------------------------------------------------------------------
namespace {
constexpr int B_  = 16384;
constexpr int SD  = 128;
constexpr int EK  = 10;
constexpr int K1  = SD * EK;   // 1280
constexpr int H   = 2048;
constexpr int N3  = 320;
constexpr int AD  = 32;
constexpr int DK  = 10;

constexpr int BM     = 128;
constexpr int BK     = 32;
constexpr int PAD    = 4;
constexpr int LDA    = BK + PAD;   // 36-float smem row stride (bank-shift 4/row)
constexpr int STAGES = 3;

constexpr int TBL    = 4096;
constexpr float TRNG = 14.0f;
}

// Scratch (no cudaMalloc allowed)
__device__ float g_spine[B_ * K1];
__device__ float g_h1[B_ * H];
__device__ float g_h2[B_ * H];
__device__ float g_a3[B_ * N3];
__device__ float g_w1[H * K1];
__device__ float g_w2[H * H];
__device__ float g_w3[N3 * H];
__device__ float g_table[TBL + 1];
__device__ float g_rstd[K1];

// ---------------------------------------------------------------------------
// PTX helpers (sm_80+ only — harness targets compute_100, no tcgen05)
// ---------------------------------------------------------------------------
__device__ __forceinline__ uint32_t smem_u32(const void* p) {
    uint32_t a;
    asm("{ .reg .u64 t; cvta.to.shared.u64 t, %1; cvt.u32.u64 %0, t; }"
        : "=r"(a) : "l"(p));
    return a;
}
__device__ __forceinline__ void cp_async16(uint32_t dst, const void* src) {
    asm volatile("cp.async.cg.shared.global [%0], [%1], 16;\n"
                 :: "r"(dst), "l"(src));
}
__device__ __forceinline__ void cp_commit() {
    asm volatile("cp.async.commit_group;\n" ::: "memory");
}
template <int N>
__device__ __forceinline__ void cp_wait_group() {
    asm volatile("cp.async.wait_group %0;\n" :: "n"(N) : "memory");
}
__device__ __forceinline__ float cvt_tf32_f(float x) {
    uint32_t r;
    asm("cvt.rna.tf32.f32 %0, %1;" : "=r"(r) : "f"(x));
    return __uint_as_float(r);
}
// ldmatrix x4: four 8x8 b16 tiles == four 8x4 f32 quadrants; delivers the
// tf32 mma fragment layout (thread -> row=lane>>2, col=lane&3) exactly.
__device__ __forceinline__ void ldsm_x4(uint32_t& r0, uint32_t& r1,
                                        uint32_t& r2, uint32_t& r3,
                                        uint32_t addr) {
    asm volatile(
        "ldmatrix.sync.aligned.m8n8.x4.shared.b16 {%0,%1,%2,%3}, [%4];"
        : "=r"(r0), "=r"(r1), "=r"(r2), "=r"(r3) : "r"(addr));
}
// Operands pre-rounded to tf32 (RNA) in memory -> feed raw bits, HW RZ is identity.
__device__ __forceinline__ void mma_tf32(float* c, const uint32_t* a,
                                         const uint32_t* b) {
    asm volatile(
        "mma.sync.aligned.m16n8k8.row.col.f32.tf32.tf32.f32 "
        "{%0,%1,%2,%3}, {%4,%5,%6,%7}, {%8,%9}, {%0,%1,%2,%3};"
        : "+f"(c[0]), "+f"(c[1]), "+f"(c[2]), "+f"(c[3])
        : "r"(a[0]), "r"(a[1]), "r"(a[2]), "r"(a[3]), "r"(b[0]), "r"(b[1]));
}

// ---------------------------------------------------------------------------
// Init: sigmoid table + reciprocal std
// ---------------------------------------------------------------------------
__global__ void init_tables_kernel(const float* __restrict__ stdv) {
    const int i = blockIdx.x * blockDim.x + threadIdx.x;
    if (i <= TBL) {
        const float x = -TRNG + (2.0f * TRNG) * (float)i / (float)TBL;
        g_table[i] = 1.0f / (1.0f + expf(-x));
    }
    if (i < K1) g_rstd[i] = 1.0f / stdv[i];
}

// ---------------------------------------------------------------------------
// RNA-round weights into scratch (once per launch)
// ---------------------------------------------------------------------------
__global__ __launch_bounds__(256) void round_weights_kernel(
    const float* __restrict__ w1, const float* __restrict__ w2,
    const float* __restrict__ w3)
{
    constexpr int N1 = H * K1, N2 = H * H, N3E = N3 * H;
    const int stride = gridDim.x * blockDim.x;
    for (int i = blockIdx.x * blockDim.x + threadIdx.x; i < N1 / 4; i += stride) {
        float4 v = reinterpret_cast<const float4*>(w1)[i];
        v.x = cvt_tf32_f(v.x); v.y = cvt_tf32_f(v.y);
        v.z = cvt_tf32_f(v.z); v.w = cvt_tf32_f(v.w);
        reinterpret_cast<float4*>(g_w1)[i] = v;
    }
    for (int i = blockIdx.x * blockDim.x + threadIdx.x; i < N2 / 4; i += stride) {
        float4 v = reinterpret_cast<const float4*>(w2)[i];
        v.x = cvt_tf32_f(v.x); v.y = cvt_tf32_f(v.y);
        v.z = cvt_tf32_f(v.z); v.w = cvt_tf32_f(v.w);
        reinterpret_cast<float4*>(g_w2)[i] = v;
    }
    for (int i = blockIdx.x * blockDim.x + threadIdx.x; i < N3E / 4; i += stride) {
        float4 v = reinterpret_cast<const float4*>(w3)[i];
        v.x = cvt_tf32_f(v.x); v.y = cvt_tf32_f(v.y);
        v.z = cvt_tf32_f(v.z); v.w = cvt_tf32_f(v.w);
        reinterpret_cast<float4*>(g_w3)[i] = v;
    }
}

// ---------------------------------------------------------------------------
// Encoder: spine = tf32_rna(sigmoid((state - mean) * rstd)) via interp table
// ---------------------------------------------------------------------------
__global__ __launch_bounds__(256) void encode_kernel(
    const float* __restrict__ state, const float* __restrict__ mean,
    float* __restrict__ spine)
{
    __shared__ float tbl[TBL + 4];
    __shared__ float s_mean[K1];
    __shared__ float s_rstd[K1];
    for (int i = threadIdx.x; i <= TBL; i += 256) tbl[i] = g_table[i];
    for (int i = threadIdx.x; i < K1; i += 256) {
        s_mean[i] = mean[i];
        s_rstd[i] = g_rstd[i];
    }
    __syncthreads();

    constexpr float SCALE = (float)TBL / (2.0f * TRNG);
    const int total4 = B_ * K1 / 4;
    for (int idx4 = blockIdx.x * blockDim.x + threadIdx.x; idx4 < total4;
         idx4 += gridDim.x * blockDim.x) {
        const int base = idx4 * 4;
        const int b  = base / K1;
        const int k0 = base - b * K1;
        float4 o;
        float* op = reinterpret_cast<float*>(&o);
        #pragma unroll
        for (int j = 0; j < 4; j++) {
            const int k = k0 + j;
            const int d = k / EK;
            const float x = (state[b * SD + d] - s_mean[k]) * s_rstd[k];
            float t = (x + TRNG) * SCALE;
            t = fminf(fmaxf(t, 0.0f), (float)TBL - 0.0001f);
            const int i = (int)t;
            const float f = t - (float)i;
            op[j] = cvt_tf32_f(fmaf(f, tbl[i + 1] - tbl[i], tbl[i]));
        }
        *reinterpret_cast<float4*>(&spine[base]) = o;
    }
}

// ---------------------------------------------------------------------------
// tf32 mma.sync GEMM with ldmatrix fragment loads.
//   Tile BM x BN x 32, 8 warps (2 M x 4 N), 3-stage cp.async pipeline.
//   Per kk-step: 4 + NT/2 ldmatrix.x4 instead of 24 scalar LDS.
// ---------------------------------------------------------------------------
template <int BN, int NDIM, int KDIM, bool RELU, bool ROUND_OUT>
__global__ __launch_bounds__(256, 2) void gemm_mma(
    const float* __restrict__ A, const float* __restrict__ W,
    const float* __restrict__ bias, float* __restrict__ out)
{
    constexpr int STRIDE = (BM + BN) * LDA;       // floats per stage
    constexpr int NT = BN / 32;                   // 8-wide n-tiles per warp
    constexpr int NP = NT / 2;                    // ldmatrix tn-pairs
    constexpr int nK = KDIM / BK;
    extern __shared__ float sm[];

    const int tid  = threadIdx.x;
    const int lane = tid & 31;
    const int wid  = tid >> 5;
    const int bm = blockIdx.y * BM;
    const int bn = blockIdx.x * BN;
    const int wm = (wid >> 2) * 64;
    const int wn = (wid & 3) * (BN / 4);
    const int ar = lane >> 2;
    const int ac = lane & 3;

    const uint32_t smb = smem_u32(sm);
    // ldmatrix per-lane addresses (bytes):
    //  A: quadrants (rows,+8) x (k,+4): bit3 -> row+8, bit4 -> k+4
    const uint32_t a_lane = smb +
        4u * ((wm + ((lane >> 3) & 1) * 8 + (lane & 7)) * LDA + (lane >> 4) * 4);
    //  B: (tn, tn+1) pair in one x4: bit3 -> k+4, bit4 -> n+8
    const uint32_t b_lane = smb + 4u * (BM * LDA) +
        4u * ((wn + (lane >> 4) * 8 + (lane & 7)) * LDA + ((lane >> 3) & 1) * 4);

    float acc[4][NT][4];
    #pragma unroll
    for (int i = 0; i < 4; i++)
        #pragma unroll
        for (int j = 0; j < NT; j++)
            #pragma unroll
            for (int m = 0; m < 4; m++) acc[i][j][m] = 0.0f;

    auto load_stage = [&](int s, int kc) {
        float* As = sm + s * STRIDE;
        float* Bs = As + BM * LDA;
        const int k0 = kc * BK;
        #pragma unroll 4
        for (int q = tid; q < BM * 8; q += 256) {
            const int r = q >> 3, c = q & 7;
            cp_async16(smem_u32(As + r * LDA + c * 4),
                       A + (size_t)(bm + r) * KDIM + k0 + c * 4);
        }
        #pragma unroll 4
        for (int q = tid; q < BN * 8; q += 256) {
            const int r = q >> 3, c = q & 7;
            cp_async16(smem_u32(Bs + r * LDA + c * 4),
                       W + (size_t)(bn + r) * KDIM + k0 + c * 4);
        }
    };

    #pragma unroll
    for (int s = 0; s < STAGES - 1; s++) { load_stage(s, s); cp_commit(); }

    for (int k = 0; k < nK; k++) {
        cp_wait_group<STAGES - 2>();
        __syncthreads();

        // Issue next-stage cp.async first (2-iteration latency slack).
        const int kn = k + STAGES - 1;
        if (kn < nK) load_stage(kn % STAGES, kn);
        cp_commit();

        const uint32_t stg = (uint32_t)((k % STAGES) * STRIDE * 4);
        #pragma unroll
        for (int kk = 0; kk < BK / 8; kk++) {
            uint32_t af[4][4], bf[NT][2];
            #pragma unroll
            for (int tm = 0; tm < 4; tm++)
                ldsm_x4(af[tm][0], af[tm][1], af[tm][2], af[tm][3],
                        a_lane + stg + (uint32_t)(tm * 16 * LDA + kk * 8) * 4);
            #pragma unroll
            for (int tp = 0; tp < NP; tp++)
                ldsm_x4(bf[tp * 2][0], bf[tp * 2][1],
                        bf[tp * 2 + 1][0], bf[tp * 2 + 1][1],
                        b_lane + stg + (uint32_t)(tp * 16 * LDA + kk * 8) * 4);
            #pragma unroll
            for (int tm = 0; tm < 4; tm++)
                #pragma unroll
                for (int tn = 0; tn < NT; tn++)
                    mma_tf32(acc[tm][tn], af[tm], bf[tn]);
        }
    }

    // Epilogue: bias + activation (+ optional tf32 rounding), float2 stores.
    #pragma unroll
    for (int tm = 0; tm < 4; tm++) {
        const int row0 = bm + wm + tm * 16 + ar;
        #pragma unroll
        for (int tn = 0; tn < NT; tn++) {
            const int col = bn + wn + tn * 8 + ac * 2;
            const float bx = bias[col];
            const float by = bias[col + 1];
            float* c = acc[tm][tn];
            float2 v0, v1;
            v0.x = c[0] + bx; v0.y = c[1] + by;
            v1.x = c[2] + bx; v1.y = c[3] + by;
            if (RELU) {
                v0.x = v0.x > 0.0f ? v0.x : 0.0f;
                v0.y = v0.y > 0.0f ? v0.y : 0.0f;
                v1.x = v1.x > 0.0f ? v1.x : 0.0f;
                v1.y = v1.y > 0.0f ? v1.y : 0.0f;
            }
            if (ROUND_OUT) {
                v0.x = cvt_tf32_f(v0.x); v0.y = cvt_tf32_f(v0.y);
                v1.x = cvt_tf32_f(v1.x); v1.y = cvt_tf32_f(v1.y);
            }
            *reinterpret_cast<float2*>(&out[(size_t)row0 * NDIM + col]) = v0;
            *reinterpret_cast<float2*>(&out[(size_t)(row0 + 8) * NDIM + col]) = v1;
        }
    }
}

// ---------------------------------------------------------------------------
// Decoder: out[b,a] = tanh(sum_j a3[b, a*DK+j] * Wd[a*DK+j] + bd[a])
// ---------------------------------------------------------------------------
__global__ __launch_bounds__(256) void decode_kernel(
    const float* __restrict__ a3, const float* __restrict__ Wd,
    const float* __restrict__ bd, float* __restrict__ out)
{
    const int idx = blockIdx.x * blockDim.x + threadIdx.x;
    if (idx >= B_ * AD) return;
    const int b = idx >> 5;
    const int a = idx & 31;
    float s = bd[a];
    #pragma unroll
    for (int j = 0; j < DK; j++)
        s = fmaf(a3[b * N3 + a * DK + j], Wd[a * DK + j], s);
    out[idx] = tanhf(s);
}

// ---------------------------------------------------------------------------
extern "C" void kernel_launch(void* const* d_in, const int* in_sizes, int n_in,
                              void* d_out, int out_size)
{
    const float* state = (const float*)d_in[0];
    const float* mean  = (const float*)d_in[1];
    const float* stdv  = (const float*)d_in[2];
    const float* W1    = (const float*)d_in[3];
    const float* b1    = (const float*)d_in[4];
    const float* W2    = (const float*)d_in[5];
    const float* b2    = (const float*)d_in[6];
    const float* W3    = (const float*)d_in[7];
    const float* b3    = (const float*)d_in[8];
    const float* Wd    = (const float*)d_in[9];
    const float* bd    = (const float*)d_in[10];
    float* out = (float*)d_out;

    float *spine, *h1, *h2, *a3, *w1r, *w2r, *w3r;
    cudaGetSymbolAddress((void**)&spine, g_spine);
    cudaGetSymbolAddress((void**)&h1, g_h1);
    cudaGetSymbolAddress((void**)&h2, g_h2);
    cudaGetSymbolAddress((void**)&a3, g_a3);
    cudaGetSymbolAddress((void**)&w1r, g_w1);
    cudaGetSymbolAddress((void**)&w2r, g_w2);
    cudaGetSymbolAddress((void**)&w3r, g_w3);

    constexpr int SMEM_128 = STAGES * (BM + 128) * LDA * sizeof(float); // 110592
    constexpr int SMEM_64  = STAGES * (BM + 64)  * LDA * sizeof(float); //  82944
    static bool attr_done = false;
    if (!attr_done) {
        cudaFuncSetAttribute(gemm_mma<128, H, K1, true, true>,
                             cudaFuncAttributeMaxDynamicSharedMemorySize, SMEM_128);
        cudaFuncSetAttribute(gemm_mma<128, H, H, true, true>,
                             cudaFuncAttributeMaxDynamicSharedMemorySize, SMEM_128);
        cudaFuncSetAttribute(gemm_mma<64, N3, H, false, false>,
                             cudaFuncAttributeMaxDynamicSharedMemorySize, SMEM_64);
        attr_done = true;
    }

    init_tables_kernel<<<(TBL + 256) / 256, 256>>>(stdv);
    round_weights_kernel<<<1024, 256>>>(W1, W2, W3);
    encode_kernel<<<2048, 256>>>(state, mean, spine);

    dim3 blk(256);
    gemm_mma<128, H, K1, true, true>
        <<<dim3(H / 128, B_ / BM), blk, SMEM_128>>>(spine, w1r, b1, h1);
    gemm_mma<128, H, H, true, true>
        <<<dim3(H / 128, B_ / BM), blk, SMEM_128>>>(h1, w2r, b2, h2);
    gemm_mma<64, N3, H, false, false>
        <<<dim3(N3 / 64, B_ / BM), blk, SMEM_64>>>(h2, w3r, b3, a3);

    decode_kernel<<<(B_ * AD + 255) / 256, 256>>>(a3, Wd, bd, out);
}